// round 5
// baseline (speedup 1.0000x reference)
#include <cuda_runtime.h>

// EdgeNetwork fused kernel for GB300 (sm_103a)
//
// Strategy:
//  1) precompute_kernel: P1[n] = b1 + NF[n] @ W1[0:64], P2[n] = NF[n] @ W1[64:128]
//     into __device__ scratch (25.6MB, L2-resident).
//  2) edge_kernel: warp processes 8 edges; gather P1[src]+P2[dst], add ea@W1c
//     (16x64 mini-GEMM from smem), LN+leaky, 64x64 GEMM vs smem W2 with
//     8-edge register blocking and f32x2 packed FMAs, LN+leaky, dot with W3.
//
// NOTE: edge_index is int32 on device (JAX demotes int64 without x64 mode).

typedef unsigned long long u64;

#define DEVINL __device__ __forceinline__
#define FULLM 0xffffffffu

DEVINL u64 f2pack(float x, float y) {
    u64 d; asm("mov.b64 %0, {%1, %2};" : "=l"(d) : "f"(x), "f"(y)); return d;
}
DEVINL void f2unpack(u64 d, float &x, float &y) {
    asm("mov.b64 {%0, %1}, %2;" : "=f"(x), "=f"(y) : "l"(d));
}
DEVINL u64 f2fma(u64 a, u64 b, u64 c) {
    u64 d; asm("fma.rn.f32x2 %0, %1, %2, %3;" : "=l"(d) : "l"(a), "l"(b), "l"(c)); return d;
}
DEVINL u64 f2add(u64 a, u64 b) {
    u64 d; asm("add.rn.f32x2 %0, %1, %2;" : "=l"(d) : "l"(a), "l"(b)); return d;
}
DEVINL u64 f2dup(float x) { return f2pack(x, x); }

#define MAXN 50000
__device__ float g_P1[MAXN * 64];
__device__ float g_P2[MAXN * 64];

// ---------------------------------------------------------------------------
// Kernel 1: per-node precompute.  P1 = b1 + NF @ W1a, P2 = NF @ W1b
// ---------------------------------------------------------------------------
__global__ __launch_bounds__(256) void precompute_kernel(
    const float* __restrict__ NF, const float* __restrict__ W1,
    const float* __restrict__ b1, int n_nodes)
{
    __shared__ __align__(16) float sWa[4096];   // W1 rows 0..63   [k][c]
    __shared__ __align__(16) float sWb[4096];   // W1 rows 64..127 [k][c]
    __shared__ __align__(16) float sNF[8][68];  // per-warp node row (padded)

    int tid = threadIdx.x;
    for (int i = tid; i < 1024; i += 256) {
        ((float4*)sWa)[i] = ((const float4*)W1)[i];
        ((float4*)sWb)[i] = ((const float4*)(W1 + 4096))[i];
    }
    __syncthreads();

    int l = tid & 31, w = tid >> 5;
    int gw = blockIdx.x * 8 + w;
    int totW = gridDim.x * 8;
    u64 b1p = f2pack(b1[2 * l], b1[2 * l + 1]);

    const u64* wa = (const u64*)sWa;
    const u64* wb = (const u64*)sWb;

    for (int n = gw; n < n_nodes && n < MAXN; n += totW) {
        float2 v = ((const float2*)(NF + (size_t)n * 64))[l];
        sNF[w][2 * l] = v.x; sNF[w][2 * l + 1] = v.y;
        __syncwarp();

        u64 acc1 = b1p, acc2 = 0ull;
        #pragma unroll
        for (int k4 = 0; k4 < 16; k4++) {
            float4 x = ((const float4*)sNF[w])[k4];
            int k = 4 * k4;
            u64 x0 = f2dup(x.x), x1 = f2dup(x.y), x2 = f2dup(x.z), x3 = f2dup(x.w);
            acc1 = f2fma(x0, wa[(k + 0) * 32 + l], acc1);
            acc2 = f2fma(x0, wb[(k + 0) * 32 + l], acc2);
            acc1 = f2fma(x1, wa[(k + 1) * 32 + l], acc1);
            acc2 = f2fma(x1, wb[(k + 1) * 32 + l], acc2);
            acc1 = f2fma(x2, wa[(k + 2) * 32 + l], acc1);
            acc2 = f2fma(x2, wb[(k + 2) * 32 + l], acc2);
            acc1 = f2fma(x3, wa[(k + 3) * 32 + l], acc1);
            acc2 = f2fma(x3, wb[(k + 3) * 32 + l], acc2);
        }
        ((u64*)(g_P1 + ((size_t)n << 6)))[l] = acc1;
        ((u64*)(g_P2 + ((size_t)n << 6)))[l] = acc2;
        __syncwarp();   // protect sNF overwrite on next iteration
    }
}

// ---------------------------------------------------------------------------
// Kernel 2: per-edge fused MLP. One warp = 8 edges. Lane l owns cols 2l,2l+1.
// ---------------------------------------------------------------------------
__global__ __launch_bounds__(128, 4) void edge_kernel(
    const int* __restrict__ EI, const float* __restrict__ EA,
    const float* __restrict__ W1, const float* __restrict__ W2,
    const float* __restrict__ g1, const float* __restrict__ be1,
    const float* __restrict__ b2, const float* __restrict__ g2,
    const float* __restrict__ be2, const float* __restrict__ W3,
    const float* __restrict__ b3, float* __restrict__ OUT, int E)
{
    __shared__ __align__(16) float sW2f[4096];   // W2 [k][c]
    __shared__ __align__(16) float sW1cf[1024];  // W1 rows 128..143 [k][c]
    __shared__ __align__(16) float sG1[64], sBe1[64], sB2[64], sG2[64], sBe2[64], sW3f[64];
    __shared__ float sB3;
    // duplicated-value staging: [warp][k][t] holds {v,v}; row padded to 10 for banks
    __shared__ __align__(16) u64 sXD[4][64][10];
    __shared__ __align__(16) u64 sEAD[4][16][10];

    int tid = threadIdx.x;
    for (int i = tid; i < 1024; i += 128) ((float4*)sW2f)[i] = ((const float4*)W2)[i];
    for (int i = tid; i < 256; i += 128)
        ((float4*)sW1cf)[i] = ((const float4*)(W1 + 8192))[i];
    if (tid < 64) {
        sG1[tid] = g1[tid]; sBe1[tid] = be1[tid]; sB2[tid] = b2[tid];
        sG2[tid] = g2[tid]; sBe2[tid] = be2[tid]; sW3f[tid] = W3[tid];
    }
    if (tid == 0) sB3 = b3[0];
    __syncthreads();

    int l = tid & 31, w = tid >> 5;
    int gw = blockIdx.x * 4 + w, totW = gridDim.x * 4;
    int nG = (E + 7) >> 3;

    float2 g1v  = ((const float2*)sG1)[l];
    float2 be1v = ((const float2*)sBe1)[l];
    float2 g2v  = ((const float2*)sG2)[l];
    float2 be2v = ((const float2*)sBe2)[l];
    float2 w3v  = ((const float2*)sW3f)[l];
    u64 b2p = ((const u64*)sB2)[l];
    float bias3 = sB3;
    const u64* w1c = (const u64*)sW1cf;
    const u64* w2p = (const u64*)sW2f;

    for (int g = gw; g < nG; g += totW) {
        int e0 = g << 3;

        // ---- load edge indices (lanes 0-7: src t, lanes 8-15: dst t) ----
        int idx = 0;
        if (l < 16) {
            int col = min(e0 + (l & 7), E - 1);
            idx = EI[(size_t)(l >> 3) * (size_t)E + (size_t)col];
        }

        // ---- gather P1[src] + P2[dst] ----
        u64 acc[8];
        #pragma unroll
        for (int t = 0; t < 8; t++) {
            int s = __shfl_sync(FULLM, idx, t);
            int d = __shfl_sync(FULLM, idx, 8 + t);
            u64 a = *(const u64*)(g_P1 + ((size_t)s << 6) + 2 * l);
            u64 b = *(const u64*)(g_P2 + ((size_t)d << 6) + 2 * l);
            acc[t] = f2add(a, b);
        }

        // ---- stage edge_attr (duplicated) ----
        {
            int t = l >> 2, k0 = (l & 3) << 2;
            int e = min(e0 + t, E - 1);
            float4 ev = *(const float4*)(EA + ((size_t)e << 4) + k0);
            sEAD[w][k0 + 0][t] = f2dup(ev.x);
            sEAD[w][k0 + 1][t] = f2dup(ev.y);
            sEAD[w][k0 + 2][t] = f2dup(ev.z);
            sEAD[w][k0 + 3][t] = f2dup(ev.w);
        }
        __syncwarp();

        // ---- ea @ W1c  (16 x 64) ----
        #pragma unroll
        for (int k = 0; k < 16; k++) {
            u64 wv = w1c[k * 32 + l];
            const ulonglong2* xp = (const ulonglong2*)&sEAD[w][k][0];
            ulonglong2 q0 = xp[0], q1 = xp[1], q2 = xp[2], q3 = xp[3];
            acc[0] = f2fma(q0.x, wv, acc[0]);
            acc[1] = f2fma(q0.y, wv, acc[1]);
            acc[2] = f2fma(q1.x, wv, acc[2]);
            acc[3] = f2fma(q1.y, wv, acc[3]);
            acc[4] = f2fma(q2.x, wv, acc[4]);
            acc[5] = f2fma(q2.y, wv, acc[5]);
            acc[6] = f2fma(q3.x, wv, acc[6]);
            acc[7] = f2fma(q3.y, wv, acc[7]);
        }

        // ---- LayerNorm 1 + leaky ----
        float hx[8], hy[8], sums[8], sqs[8];
        #pragma unroll
        for (int t = 0; t < 8; t++) {
            float x, y; f2unpack(acc[t], x, y);
            hx[t] = x; hy[t] = y;
            sums[t] = x + y;
            sqs[t] = x * x + y * y;
        }
        #pragma unroll
        for (int r = 0; r < 5; r++) {
            int o = 16 >> r;
            #pragma unroll
            for (int t = 0; t < 8; t++) {
                sums[t] += __shfl_xor_sync(FULLM, sums[t], o);
                sqs[t]  += __shfl_xor_sync(FULLM, sqs[t], o);
            }
        }
        #pragma unroll
        for (int t = 0; t < 8; t++) {
            float mean = sums[t] * 0.015625f;
            float var  = fmaf(sqs[t], 0.015625f, -mean * mean);
            float rstd = rsqrtf(var + 1e-5f);
            float h0 = fmaf(hx[t] - mean, rstd * g1v.x, be1v.x);
            float h1 = fmaf(hy[t] - mean, rstd * g1v.y, be1v.y);
            hx[t] = fmaxf(h0, 0.1f * h0);
            hy[t] = fmaxf(h1, 0.1f * h1);
        }

        __syncwarp();   // all lanes done reading sXD from previous iteration
        {
            ulonglong2* r0 = (ulonglong2*)&sXD[w][2 * l][0];
            ulonglong2* r1 = (ulonglong2*)&sXD[w][2 * l + 1][0];
            r0[0] = make_ulonglong2(f2dup(hx[0]), f2dup(hx[1]));
            r0[1] = make_ulonglong2(f2dup(hx[2]), f2dup(hx[3]));
            r0[2] = make_ulonglong2(f2dup(hx[4]), f2dup(hx[5]));
            r0[3] = make_ulonglong2(f2dup(hx[6]), f2dup(hx[7]));
            r1[0] = make_ulonglong2(f2dup(hy[0]), f2dup(hy[1]));
            r1[1] = make_ulonglong2(f2dup(hy[2]), f2dup(hy[3]));
            r1[2] = make_ulonglong2(f2dup(hy[4]), f2dup(hy[5]));
            r1[3] = make_ulonglong2(f2dup(hy[6]), f2dup(hy[7]));
        }
        __syncwarp();

        // ---- h1 @ W2  (64 x 64) ----
        u64 acc2[8];
        #pragma unroll
        for (int t = 0; t < 8; t++) acc2[t] = b2p;
        #pragma unroll 8
        for (int k = 0; k < 64; k++) {
            u64 wv = w2p[k * 32 + l];
            const ulonglong2* xp = (const ulonglong2*)&sXD[w][k][0];
            ulonglong2 q0 = xp[0], q1 = xp[1], q2 = xp[2], q3 = xp[3];
            acc2[0] = f2fma(q0.x, wv, acc2[0]);
            acc2[1] = f2fma(q0.y, wv, acc2[1]);
            acc2[2] = f2fma(q1.x, wv, acc2[2]);
            acc2[3] = f2fma(q1.y, wv, acc2[3]);
            acc2[4] = f2fma(q2.x, wv, acc2[4]);
            acc2[5] = f2fma(q2.y, wv, acc2[5]);
            acc2[6] = f2fma(q3.x, wv, acc2[6]);
            acc2[7] = f2fma(q3.y, wv, acc2[7]);
        }

        // ---- LayerNorm 2 + leaky + dot(W3) ----
        #pragma unroll
        for (int t = 0; t < 8; t++) {
            float x, y; f2unpack(acc2[t], x, y);
            hx[t] = x; hy[t] = y;
            sums[t] = x + y;
            sqs[t] = x * x + y * y;
        }
        #pragma unroll
        for (int r = 0; r < 5; r++) {
            int o = 16 >> r;
            #pragma unroll
            for (int t = 0; t < 8; t++) {
                sums[t] += __shfl_xor_sync(FULLM, sums[t], o);
                sqs[t]  += __shfl_xor_sync(FULLM, sqs[t], o);
            }
        }
        float px[8];
        #pragma unroll
        for (int t = 0; t < 8; t++) {
            float mean = sums[t] * 0.015625f;
            float var  = fmaf(sqs[t], 0.015625f, -mean * mean);
            float rstd = rsqrtf(var + 1e-5f);
            float h0 = fmaf(hx[t] - mean, rstd * g2v.x, be2v.x);
            float h1 = fmaf(hy[t] - mean, rstd * g2v.y, be2v.y);
            h0 = fmaxf(h0, 0.1f * h0);
            h1 = fmaxf(h1, 0.1f * h1);
            px[t] = fmaf(h0, w3v.x, h1 * w3v.y);
        }
        #pragma unroll
        for (int r = 0; r < 5; r++) {
            int o = 16 >> r;
            #pragma unroll
            for (int t = 0; t < 8; t++)
                px[t] += __shfl_xor_sync(FULLM, px[t], o);
        }
        float ov = px[0];
        #pragma unroll
        for (int t = 1; t < 8; t++) ov = (l == t) ? px[t] : ov;
        if (l < 8) {
            int e = e0 + l;
            if (e < E) OUT[e] = ov + bias3;
        }
    }
}

// ---------------------------------------------------------------------------
// Launch
// ---------------------------------------------------------------------------
extern "C" void kernel_launch(void* const* d_in, const int* in_sizes, int n_in,
                              void* d_out, int out_size)
{
    const float* NF  = (const float*)d_in[0];      // (N, 64)
    const int*   EI  = (const int*)d_in[1];        // (2, E) int32 on device
    const float* EA  = (const float*)d_in[2];      // (E, 16)
    const float* W1  = (const float*)d_in[3];      // (144, 64)
    const float* b1  = (const float*)d_in[4];
    const float* g1  = (const float*)d_in[5];
    const float* be1 = (const float*)d_in[6];
    const float* W2  = (const float*)d_in[7];      // (64, 64)
    const float* b2  = (const float*)d_in[8];
    const float* g2  = (const float*)d_in[9];
    const float* be2 = (const float*)d_in[10];
    const float* W3  = (const float*)d_in[11];     // (64, 1)
    const float* b3  = (const float*)d_in[12];
    float* OUT = (float*)d_out;

    int n_nodes = in_sizes[0] / 64;
    int E       = in_sizes[1] / 2;
    if (E <= 0) return;

    precompute_kernel<<<592, 256>>>(NF, W1, b1, n_nodes);
    edge_kernel<<<592, 128>>>(EI, EA, W1, W2, g1, be1, b2, g2, be2, W3, b3, OUT, E);
}

// round 6
// speedup vs baseline: 2.4198x; 2.4198x over previous
#include <cuda_runtime.h>

// EdgeNetwork fused kernel, tensor-core (tf32 mma.sync) version.
// 1) precompute: P1[n]=b1+NF[n]@W1[:64], P2[n]=NF[n]@W1[64:128] (device scratch)
// 2) edge_kernel: warp=16 edges; gather U=P1[src]+P2[dst] -> C frags;
//    ea@W1c via m16n8k8; LN1 in frag layout; h@W2 with W2 B-frags in regs
//    (row-permuted so C frag == next A frag), activation hi/lo split; LN2+W3.

typedef unsigned long long u64;
#define DEVINL __device__ __forceinline__
#define FULLM 0xffffffffu

DEVINL u64 f2pack(float x, float y) {
    u64 d; asm("mov.b64 %0, {%1, %2};" : "=l"(d) : "f"(x), "f"(y)); return d;
}
DEVINL u64 f2fma(u64 a, u64 b, u64 c) {
    u64 d; asm("fma.rn.f32x2 %0, %1, %2, %3;" : "=l"(d) : "l"(a), "l"(b), "l"(c)); return d;
}
DEVINL u64 f2add(u64 a, u64 b) {
    u64 d; asm("add.rn.f32x2 %0, %1, %2;" : "=l"(d) : "l"(a), "l"(b)); return d;
}
DEVINL u64 f2dup(float x) { return f2pack(x, x); }
DEVINL unsigned tf32u(float x) {
    unsigned r; asm("cvt.rna.tf32.f32 %0, %1;" : "=r"(r) : "f"(x)); return r;
}
DEVINL void mma8(float* d, unsigned a0, unsigned a1, unsigned a2, unsigned a3,
                 unsigned b0, unsigned b1) {
    asm("mma.sync.aligned.m16n8k8.row.col.f32.tf32.tf32.f32 "
        "{%0,%1,%2,%3},{%4,%5,%6,%7},{%8,%9},{%0,%1,%2,%3};"
        : "+f"(d[0]), "+f"(d[1]), "+f"(d[2]), "+f"(d[3])
        : "r"(a0), "r"(a1), "r"(a2), "r"(a3), "r"(b0), "r"(b1));
}
DEVINL float leaky(float h) { return fmaxf(h, 0.1f * h); }

#define MAXN 50000
__device__ float g_P1[MAXN * 64];
__device__ float g_P2[MAXN * 64];

// ---------------------------------------------------------------------------
__global__ __launch_bounds__(256) void precompute_kernel(
    const float* __restrict__ NF, const float* __restrict__ W1,
    const float* __restrict__ b1, int n_nodes)
{
    __shared__ __align__(16) float sWa[4096];
    __shared__ __align__(16) float sWb[4096];
    __shared__ __align__(16) float sNF[8][68];

    int tid = threadIdx.x;
    for (int i = tid; i < 1024; i += 256) {
        ((float4*)sWa)[i] = ((const float4*)W1)[i];
        ((float4*)sWb)[i] = ((const float4*)(W1 + 4096))[i];
    }
    __syncthreads();

    int l = tid & 31, w = tid >> 5;
    int gw = blockIdx.x * 8 + w, totW = gridDim.x * 8;
    u64 b1p = f2pack(b1[2 * l], b1[2 * l + 1]);
    const u64* wa = (const u64*)sWa;
    const u64* wb = (const u64*)sWb;

    for (int n = gw; n < n_nodes && n < MAXN; n += totW) {
        float2 v = ((const float2*)(NF + (size_t)n * 64))[l];
        sNF[w][2 * l] = v.x; sNF[w][2 * l + 1] = v.y;
        __syncwarp();
        u64 acc1 = b1p, acc2 = 0ull;
        #pragma unroll
        for (int k4 = 0; k4 < 16; k4++) {
            float4 x = ((const float4*)sNF[w])[k4];
            int k = 4 * k4;
            u64 x0 = f2dup(x.x), x1 = f2dup(x.y), x2 = f2dup(x.z), x3 = f2dup(x.w);
            acc1 = f2fma(x0, wa[(k + 0) * 32 + l], acc1);
            acc2 = f2fma(x0, wb[(k + 0) * 32 + l], acc2);
            acc1 = f2fma(x1, wa[(k + 1) * 32 + l], acc1);
            acc2 = f2fma(x1, wb[(k + 1) * 32 + l], acc2);
            acc1 = f2fma(x2, wa[(k + 2) * 32 + l], acc1);
            acc2 = f2fma(x2, wb[(k + 2) * 32 + l], acc2);
            acc1 = f2fma(x3, wa[(k + 3) * 32 + l], acc1);
            acc2 = f2fma(x3, wb[(k + 3) * 32 + l], acc2);
        }
        ((u64*)(g_P1 + ((size_t)n << 6)))[l] = acc1;
        ((u64*)(g_P2 + ((size_t)n << 6)))[l] = acc2;
        __syncwarp();
    }
}

// ---------------------------------------------------------------------------
// edge_kernel: warp = 16 edges. r = lane>>2 (0..7), q = lane&3.
// C-frag of m16n8k8 tile m: (r,8m+2q),(r,8m+2q+1),(r+8,8m+2q),(r+8,8m+2q+1)
// ---------------------------------------------------------------------------
__global__ __launch_bounds__(128) void edge_kernel(
    const int* __restrict__ EI, const float* __restrict__ EA,
    const float* __restrict__ W1, const float* __restrict__ W2,
    const float* __restrict__ g1, const float* __restrict__ be1,
    const float* __restrict__ b2, const float* __restrict__ g2,
    const float* __restrict__ be2, const float* __restrict__ W3,
    const float* __restrict__ b3, float* __restrict__ OUT, int E)
{
    __shared__ __align__(16) float sU[4][16][68];     // gathered U, pad 68
    __shared__ __align__(16) float sEA[4][16][20];    // edge_attr tile, pad 20
    __shared__ __align__(16) uint2 sW1c[2][8][8][5];  // W1c B frags, pad 5
    __shared__ __align__(16) float2 sQ1[64];          // (g1,be1) per col
    __shared__ __align__(16) float2 sB2p[32];         // b2 pairs
    __shared__ __align__(16) float4 sQ2[64];          // (g2,be2,w3,0) per col
    __shared__ float sB3;

    int tid = threadIdx.x;
    for (int i = tid; i < 64; i += 128) {
        sQ1[i] = make_float2(g1[i], be1[i]);
        sQ2[i] = make_float4(g2[i], be2[i], W3[i], 0.f);
    }
    for (int i = tid; i < 32; i += 128)
        sB2p[i] = make_float2(b2[2 * i], b2[2 * i + 1]);
    {
        const float* w1c = W1 + 128 * 64;
        for (int i = tid; i < 512; i += 128) {
            int qq = i & 3, rr = (i >> 2) & 7, mm = (i >> 5) & 7, jk = i >> 8;
            int col = 8 * mm + rr;
            sW1c[jk][mm][rr][qq] =
                make_uint2(tf32u(w1c[(8 * jk + qq) * 64 + col]),
                           tf32u(w1c[(8 * jk + qq + 4) * 64 + col]));
        }
    }
    if (tid == 0) sB3 = b3[0];
    __syncthreads();

    int l = tid & 31, w = tid >> 5;
    int q = l & 3, r = l >> 2;

    // W2 B-frags in registers, row-permuted: b0=W2[8kt+2q][8m+r], b1=row+1
    unsigned w2f[8][8][2];
    #pragma unroll
    for (int kt = 0; kt < 8; kt++) {
        int row0 = 8 * kt + 2 * q;
        #pragma unroll
        for (int m = 0; m < 8; m++) {
            int col = 8 * m + r;
            w2f[kt][m][0] = tf32u(W2[row0 * 64 + col]);
            w2f[kt][m][1] = tf32u(W2[(row0 + 1) * 64 + col]);
        }
    }

    int gw = blockIdx.x * 4 + w, totW = gridDim.x * 4;
    int nG = (E + 15) >> 4;
    float bias3 = sB3;

    for (int g = gw; g < nG; g += totW) {
        int e0 = g << 4;

        // 1. indices: lanes 0-15 src(t=l), 16-31 dst(t=l-16)
        int colE = e0 + (l & 15); if (colE >= E) colE = E - 1;
        int idx = EI[(size_t)(l >> 4) * (size_t)E + (size_t)colE];

        // 2. gather U rows into smem (lane owns cols 2l,2l+1)
        #pragma unroll
        for (int t = 0; t < 16; t++) {
            int s = __shfl_sync(FULLM, idx, t);
            int d = __shfl_sync(FULLM, idx, 16 + t);
            u64 a = *(const u64*)(g_P1 + ((size_t)s << 6) + 2 * l);
            u64 b = *(const u64*)(g_P2 + ((size_t)d << 6) + 2 * l);
            *(u64*)&sU[w][t][2 * l] = f2add(a, b);
        }

        // 3. stage edge_attr 16x16
        if (e0 + 16 <= E) {
            const float4* base = (const float4*)(EA + (size_t)e0 * 16);
            float4 v0 = base[l], v1 = base[l + 32];
            int rr = l >> 2, cc = (l & 3) << 2;
            *(float4*)&sEA[w][rr][cc] = v0;
            *(float4*)&sEA[w][rr + 8][cc] = v1;
        } else if (l < 16) {
            int e = e0 + l; if (e >= E) e = E - 1;
            const float4* src = (const float4*)(EA + (size_t)e * 16);
            #pragma unroll
            for (int j = 0; j < 4; j++) *(float4*)&sEA[w][l][4 * j] = src[j];
        }
        __syncwarp();

        // 4. C init from U; ea @ W1c
        float D[8][4];
        #pragma unroll
        for (int m = 0; m < 8; m++) {
            float2 u01 = *(const float2*)&sU[w][r][8 * m + 2 * q];
            float2 u23 = *(const float2*)&sU[w][r + 8][8 * m + 2 * q];
            D[m][0] = u01.x; D[m][1] = u01.y; D[m][2] = u23.x; D[m][3] = u23.y;
        }
        #pragma unroll
        for (int jk = 0; jk < 2; jk++) {
            unsigned a0 = tf32u(sEA[w][r][8 * jk + q]);
            unsigned a1 = tf32u(sEA[w][r + 8][8 * jk + q]);
            unsigned a2 = tf32u(sEA[w][r][8 * jk + q + 4]);
            unsigned a3 = tf32u(sEA[w][r + 8][8 * jk + q + 4]);
            #pragma unroll
            for (int m = 0; m < 8; m++) {
                uint2 b = sW1c[jk][m][r][q];
                mma8(D[m], a0, a1, a2, a3, b.x, b.y);
            }
        }
        __syncwarp();   // smem reads done

        // 5. LN1 stats (rows r, r+8)
        float s0 = 0.f, s1 = 0.f, q0 = 0.f, q1 = 0.f;
        #pragma unroll
        for (int m = 0; m < 8; m++) {
            s0 += D[m][0] + D[m][1];
            q0 = fmaf(D[m][0], D[m][0], q0); q0 = fmaf(D[m][1], D[m][1], q0);
            s1 += D[m][2] + D[m][3];
            q1 = fmaf(D[m][2], D[m][2], q1); q1 = fmaf(D[m][3], D[m][3], q1);
        }
        s0 += __shfl_xor_sync(FULLM, s0, 1); s0 += __shfl_xor_sync(FULLM, s0, 2);
        q0 += __shfl_xor_sync(FULLM, q0, 1); q0 += __shfl_xor_sync(FULLM, q0, 2);
        s1 += __shfl_xor_sync(FULLM, s1, 1); s1 += __shfl_xor_sync(FULLM, s1, 2);
        q1 += __shfl_xor_sync(FULLM, q1, 1); q1 += __shfl_xor_sync(FULLM, q1, 2);
        float mu0 = s0 * 0.015625f;
        float rs0 = rsqrtf(fmaf(q0, 0.015625f, -mu0 * mu0) + 1e-5f);
        float mu1 = s1 * 0.015625f;
        float rs1 = rsqrtf(fmaf(q1, 0.015625f, -mu1 * mu1) + 1e-5f);

        // 6. LN1 + leaky + hi/lo split; h @ W2 (C frag feeds A frag directly)
        float D2[8][4];
        #pragma unroll
        for (int m = 0; m < 8; m++)
            { D2[m][0] = 0.f; D2[m][1] = 0.f; D2[m][2] = 0.f; D2[m][3] = 0.f; }

        #pragma unroll
        for (int kt = 0; kt < 8; kt++) {
            float4 gb = *(const float4*)&sQ1[8 * kt + 2 * q];
            float h0 = leaky(fmaf((D[kt][0] - mu0) * rs0, gb.x, gb.y));
            float h1 = leaky(fmaf((D[kt][1] - mu0) * rs0, gb.z, gb.w));
            float h2 = leaky(fmaf((D[kt][2] - mu1) * rs1, gb.x, gb.y));
            float h3 = leaky(fmaf((D[kt][3] - mu1) * rs1, gb.z, gb.w));
            unsigned a0h = tf32u(h0), a2h = tf32u(h1);
            unsigned a1h = tf32u(h2), a3h = tf32u(h3);
            unsigned a0l = tf32u(h0 - __uint_as_float(a0h));
            unsigned a2l = tf32u(h1 - __uint_as_float(a2h));
            unsigned a1l = tf32u(h2 - __uint_as_float(a1h));
            unsigned a3l = tf32u(h3 - __uint_as_float(a3h));
            #pragma unroll
            for (int m = 0; m < 8; m++)
                mma8(D2[m], a0h, a1h, a2h, a3h, w2f[kt][m][0], w2f[kt][m][1]);
            #pragma unroll
            for (int m = 0; m < 8; m++)
                mma8(D2[m], a0l, a1l, a2l, a3l, w2f[kt][m][0], w2f[kt][m][1]);
        }

        // 7. +b2, LN2 stats
        s0 = 0.f; s1 = 0.f; q0 = 0.f; q1 = 0.f;
        #pragma unroll
        for (int m = 0; m < 8; m++) {
            float2 bb = sB2p[4 * m + q];
            D2[m][0] += bb.x; D2[m][1] += bb.y;
            D2[m][2] += bb.x; D2[m][3] += bb.y;
            s0 += D2[m][0] + D2[m][1];
            q0 = fmaf(D2[m][0], D2[m][0], q0); q0 = fmaf(D2[m][1], D2[m][1], q0);
            s1 += D2[m][2] + D2[m][3];
            q1 = fmaf(D2[m][2], D2[m][2], q1); q1 = fmaf(D2[m][3], D2[m][3], q1);
        }
        s0 += __shfl_xor_sync(FULLM, s0, 1); s0 += __shfl_xor_sync(FULLM, s0, 2);
        q0 += __shfl_xor_sync(FULLM, q0, 1); q0 += __shfl_xor_sync(FULLM, q0, 2);
        s1 += __shfl_xor_sync(FULLM, s1, 1); s1 += __shfl_xor_sync(FULLM, s1, 2);
        q1 += __shfl_xor_sync(FULLM, q1, 1); q1 += __shfl_xor_sync(FULLM, q1, 2);
        mu0 = s0 * 0.015625f;
        rs0 = rsqrtf(fmaf(q0, 0.015625f, -mu0 * mu0) + 1e-5f);
        mu1 = s1 * 0.015625f;
        rs1 = rsqrtf(fmaf(q1, 0.015625f, -mu1 * mu1) + 1e-5f);

        // 8. LN2 + leaky + W3 dot
        float acc0 = 0.f, acc1 = 0.f;
        #pragma unroll
        for (int m = 0; m < 8; m++) {
            float4 pa = sQ2[8 * m + 2 * q];
            float4 pb = sQ2[8 * m + 2 * q + 1];
            float h0 = leaky(fmaf((D2[m][0] - mu0) * rs0, pa.x, pa.y));
            float h1 = leaky(fmaf((D2[m][1] - mu0) * rs0, pb.x, pb.y));
            float h2 = leaky(fmaf((D2[m][2] - mu1) * rs1, pa.x, pa.y));
            float h3 = leaky(fmaf((D2[m][3] - mu1) * rs1, pb.x, pb.y));
            acc0 = fmaf(h0, pa.z, acc0); acc0 = fmaf(h1, pb.z, acc0);
            acc1 = fmaf(h2, pa.z, acc1); acc1 = fmaf(h3, pb.z, acc1);
        }
        acc0 += __shfl_xor_sync(FULLM, acc0, 1);
        acc0 += __shfl_xor_sync(FULLM, acc0, 2);
        acc1 += __shfl_xor_sync(FULLM, acc1, 1);
        acc1 += __shfl_xor_sync(FULLM, acc1, 2);

        if (q == 0) {
            int e = e0 + r;
            if (e < E) OUT[e] = acc0 + bias3;
            int e2 = e0 + 8 + r;
            if (e2 < E) OUT[e2] = acc1 + bias3;
        }
    }
}

// ---------------------------------------------------------------------------
extern "C" void kernel_launch(void* const* d_in, const int* in_sizes, int n_in,
                              void* d_out, int out_size)
{
    const float* NF  = (const float*)d_in[0];
    const int*   EI  = (const int*)d_in[1];        // (2,E) int32
    const float* EA  = (const float*)d_in[2];
    const float* W1  = (const float*)d_in[3];
    const float* b1  = (const float*)d_in[4];
    const float* g1  = (const float*)d_in[5];
    const float* be1 = (const float*)d_in[6];
    const float* W2  = (const float*)d_in[7];
    const float* b2  = (const float*)d_in[8];
    const float* g2  = (const float*)d_in[9];
    const float* be2 = (const float*)d_in[10];
    const float* W3  = (const float*)d_in[11];
    const float* b3  = (const float*)d_in[12];
    float* OUT = (float*)d_out;

    int n_nodes = in_sizes[0] / 64;
    int E       = in_sizes[1] / 2;
    if (E <= 0) return;

    precompute_kernel<<<592, 256>>>(NF, W1, b1, n_nodes);
    edge_kernel<<<296, 128>>>(EI, EA, W1, W2, g1, be1, b2, g2, be2, W3, b3, OUT, E);
}